// round 14
// baseline (speedup 1.0000x reference)
#include <cuda_runtime.h>
#include <math.h>

#define TT 500
#define NN 21
#define BB 64
#define THREADS 384
#define HST 20  // floats per state row (80B = 5x16B, keeps float4 alignment)

// ---------------- device scratch (c-major, packed) ----------------
__device__ __align__(16) float g_A[NN * NN];
// Q1[p*128+c] = (z(2p), r(2p), z(2p+1), r(2p+1)), p=0..63 (+pad) — lzw1/lrw1 bottom
__device__ __align__(16) float4 g_Q1[66 * 128];
// Q2[p*128+c] = (h(2p), h(2p+1)) — lhw1 bottom
__device__ __align__(16) float2 g_Q2[66 * 128];
// P4[k*128+c] = (Mz, Mr, Vz, Vr), k=0..127 (+pad)
__device__ __align__(16) float4 g_P4[130 * 128];
// Q5[p*128+c] = (Mh(2p), Vh(2p), Mh(2p+1), Vh(2p+1)), p=0..63 (+pad)
__device__ __align__(16) float4 g_Q5[66 * 128];
__device__ __align__(16) float g_c1[6 * 128];  // uz,ur,uh,czb,crb,chb
__device__ __align__(16) float g_c2[3 * 128];  // dzb,drb,dhb

// ---------------- smem ----------------
struct SM {
  float2 YP[TT * 6];
  float2 AP[6 * 22];
  float H1loc[128 * HST];
  float H1rem[128 * HST];
  float H2[128 * HST];
  float XR1[128 * HST];
  float XP[128 * HST];
  float XR2[128 * HST];
  float2 ZC[128 * 6];
  float2 PZ[128 * 13 + 8];  // layer2 partials [c*13 + h*6 + pl]
  float2 PR[128 * 13 + 8];
  float uz[128], ur[128], uh[128], czb[128], crb[128], chb[128];
  float dzb[128], drb[128], dhb[128], clsw[128];
  unsigned long long mb_full;  // H1(t) ready.  arrivals: 128 local G1 + 128 remote G1
  unsigned long long mb_free;  // pass3 readers done. arrivals: 256 local G2 + 256 remote G2
  float peer_sum;
  float red[12];
};

// ---------------- helpers ----------------
__device__ __forceinline__ float2 ffma2(float2 a, float2 b, float2 c) {
  float2 d;
  asm("fma.rn.f32x2 %0, %1, %2, %3;"
      : "=l"(reinterpret_cast<unsigned long long&>(d))
      : "l"(reinterpret_cast<unsigned long long&>(a)),
        "l"(reinterpret_cast<unsigned long long&>(b)),
        "l"(reinterpret_cast<unsigned long long&>(c)));
  return d;
}
__device__ __forceinline__ float tanha(float x) {
  float y;
  asm("tanh.approx.f32 %0, %1;" : "=f"(y) : "f"(x));
  return y;
}
__device__ __forceinline__ float sigma(float x) {
  return fmaf(tanha(0.5f * x), 0.5f, 0.5f);
}
__device__ __forceinline__ unsigned smem_u32(const void* p) {
  unsigned a;
  asm("{ .reg .u64 t; cvta.to.shared.u64 t, %1; cvt.u32.u64 %0, t; }"
      : "=r"(a) : "l"(p));
  return a;
}
__device__ __forceinline__ unsigned mapa_u32(unsigned a, unsigned r) {
  unsigned o;
  asm("mapa.shared::cluster.u32 %0, %1, %2;" : "=r"(o) : "r"(a), "r"(r));
  return o;
}
__device__ __forceinline__ void stc64(unsigned a, float2 v) {
  asm volatile("st.shared::cluster.b64 [%0], %1;"
               :: "r"(a), "l"(reinterpret_cast<const unsigned long long&>(v))
               : "memory");
}
__device__ __forceinline__ void stc32(unsigned a, float v) {
  asm volatile("st.shared::cluster.b32 [%0], %1;" :: "r"(a), "f"(v) : "memory");
}
#define CLUSTER_BAR()                                             \
  do {                                                            \
    asm volatile("barrier.cluster.arrive.aligned;" ::: "memory"); \
    asm volatile("barrier.cluster.wait.aligned;" ::: "memory");   \
  } while (0)
#define BARG1() asm volatile("bar.sync 1, 128;" ::: "memory")
#define BARG2() asm volatile("bar.sync 2, 256;" ::: "memory")
#define FENCE_CL() asm volatile("fence.acq_rel.cluster;" ::: "memory")

__device__ __forceinline__ void mb_init(unsigned a, unsigned cnt) {
  asm volatile("mbarrier.init.shared.b64 [%0], %1;" :: "r"(a), "r"(cnt)
               : "memory");
}
__device__ __forceinline__ void mb_arrive_loc(unsigned a) {
  asm volatile("mbarrier.arrive.shared.b64 _, [%0];" :: "r"(a) : "memory");
}
__device__ __forceinline__ void mb_arrive_rem(unsigned a) {
  asm volatile("mbarrier.arrive.shared::cluster.b64 _, [%0];" :: "r"(a)
               : "memory");
}
__device__ __forceinline__ void mb_wait(unsigned a, unsigned par) {
  unsigned done = 0;
  do {
    asm volatile(
        "{\n\t.reg .pred p;\n\t"
        "mbarrier.try_wait.parity.acquire.cta.shared::cta.b64 p, [%1], %2;\n\t"
        "selp.b32 %0, 1, 0, p;\n\t}"
        : "=r"(done) : "r"(a), "r"(par) : "memory");
  } while (!done);
}

// ---- load one state row's node-pairs ----
template <int NP>
__device__ __forceinline__ void ldrow2(const float* __restrict__ r, float2* v) {
  float4 a = *reinterpret_cast<const float4*>(r);
  float4 b = *reinterpret_cast<const float4*>(r + 4);
  v[0] = make_float2(a.x, a.y);
  v[1] = make_float2(a.z, a.w);
  v[2] = make_float2(b.x, b.y);
  v[3] = make_float2(b.z, b.w);
  if (NP == 5) {
    float2 cq = *reinterpret_cast<const float2*>(r + 8);
    v[4] = cq;
  }
  if (NP == 6) {
    float4 cq = *reinterpret_cast<const float4*>(r + 8);
    v[4] = make_float2(cq.x, cq.y);
    v[5] = make_float2(cq.z, cq.w);
  }
}
template <int NP>
__device__ __forceinline__ void acc_g(const float2* v, float w, float2* a) {
  float2 w2 = make_float2(w, w);
#pragma unroll
  for (int p = 0; p < NP; p++) a[p] = ffma2(v[p], w2, a[p]);
}

// ---------------- merged prep kernel ----------------
__global__ void prep_all(
    int E, const int* __restrict__ ei, const float* __restrict__ ew,
    const float* Wz1, const float* bz1, const float* lzw1, const float* lzb1,
    const float* Wr1, const float* br1, const float* lrw1, const float* lrb1,
    const float* Wh1, const float* bh1, const float* lhw1, const float* lhb1,
    const float* Wz2, const float* bz2, const float* lzw2, const float* lzb2,
    const float* Wr2, const float* br2, const float* lrw2, const float* lrb2,
    const float* Wh2, const float* bh2, const float* lhw2, const float* lhb2) {
  if (blockIdx.x == 0 && threadIdx.x == 0) {
    float deg[NN], dinv[NN];
    for (int n = 0; n < NN; n++) deg[n] = 1.0f;
    for (int e = 0; e < E; e++) deg[ei[E + e]] += ew[e];
    for (int n = 0; n < NN; n++) dinv[n] = (deg[n] > 0.f) ? rsqrtf(deg[n]) : 0.f;
    for (int i = 0; i < NN * NN; i++) g_A[i] = 0.f;
    for (int e = 0; e < E; e++) {
      int sN = ei[e], d = ei[E + e];
      g_A[d * NN + sN] += dinv[sN] * ew[e] * dinv[d];
    }
    for (int n = 0; n < NN; n++) g_A[n * NN + n] += dinv[n] * dinv[n];
  }
  int t0 = blockIdx.x * blockDim.x + threadIdx.x;
  int nt = gridDim.x * blockDim.x;

  for (int i = t0; i < 66 * 128; i += nt) {
    int c = i & 127, p = i >> 7;
    int ka = 2 * p, kb = 2 * p + 1;
    if (ka < 128) {
      g_Q1[i] = make_float4(lzw1[(128 + ka) * 128 + c], lrw1[(128 + ka) * 128 + c],
                            lzw1[(128 + kb) * 128 + c], lrw1[(128 + kb) * 128 + c]);
      g_Q2[i] = make_float2(lhw1[(128 + ka) * 128 + c],
                            lhw1[(128 + kb) * 128 + c]);
      float m0 = 0.f, m1 = 0.f;
      for (int m = 0; m < 128; m++) {
        m0 += Wh2[ka * 128 + m] * lhw2[m * 128 + c];
        m1 += Wh2[kb * 128 + m] * lhw2[m * 128 + c];
      }
      g_Q5[i] = make_float4(m0, lhw2[(128 + ka) * 128 + c], m1,
                            lhw2[(128 + kb) * 128 + c]);
    } else {
      g_Q1[i] = make_float4(0.f, 0.f, 0.f, 0.f);
      g_Q2[i] = make_float2(0.f, 0.f);
      g_Q5[i] = make_float4(0.f, 0.f, 0.f, 0.f);
    }
  }
  for (int i = t0; i < 130 * 128; i += nt) {
    int c = i & 127, k = i >> 7;
    if (k < 128) {
      float mz = 0.f, mr = 0.f;
      for (int m = 0; m < 128; m++) {
        mz += Wz2[k * 128 + m] * lzw2[m * 128 + c];
        mr += Wr2[k * 128 + m] * lrw2[m * 128 + c];
      }
      g_P4[i] = make_float4(mz, mr, lzw2[(128 + k) * 128 + c],
                            lrw2[(128 + k) * 128 + c]);
    } else {
      g_P4[i] = make_float4(0.f, 0.f, 0.f, 0.f);
    }
  }
  for (int c = t0; c < 128; c += nt) {
    float uz = 0, ur = 0, uh = 0, cz = 0, cr = 0, ch = 0, dz = 0, dr = 0, dh = 0;
    for (int m = 0; m < 128; m++) {
      uz += Wz1[m] * lzw1[m * 128 + c];
      ur += Wr1[m] * lrw1[m * 128 + c];
      uh += Wh1[m] * lhw1[m * 128 + c];
      cz += bz1[m] * lzw1[m * 128 + c];
      cr += br1[m] * lrw1[m * 128 + c];
      ch += bh1[m] * lhw1[m * 128 + c];
      dz += bz2[m] * lzw2[m * 128 + c];
      dr += br2[m] * lrw2[m * 128 + c];
      dh += bh2[m] * lhw2[m * 128 + c];
    }
    g_c1[0 * 128 + c] = uz;
    g_c1[1 * 128 + c] = ur;
    g_c1[2 * 128 + c] = uh;
    g_c1[3 * 128 + c] = cz + lzb1[c];
    g_c1[4 * 128 + c] = cr + lrb1[c];
    g_c1[5 * 128 + c] = ch + lhb1[c];
    g_c2[0 * 128 + c] = dz + lzb2[c];
    g_c2[1 * 128 + c] = dr + lrb2[c];
    g_c2[2 * 128 + c] = dh + lhb2[c];
  }
}

// ---------------- G1: layer-1 producer (128 threads, thread = column c) ----
template <int NP, int RANK>
__device__ void g1_run(SM* __restrict__ s, const int c, const unsigned peer_h1,
                       const unsigned loc_full, const unsigned peer_full,
                       const unsigned loc_free) {
  const float uzv = s->uz[c], urv = s->ur[c], uhv = s->uh[c];
  const float czv = s->czb[c], crv = s->crb[c], chv = s->chb[c];

  for (int t = 0; t < TT; t++) {
    float2 zg[NP], h1v[NP], yv[NP];
    // ---- pass 1: z & r gates, full-k dot over H1loc ----
    {
      float2 az[NP], ar[NP];
#pragma unroll
      for (int p = 0; p < NP; p++) az[p] = ar[p] = make_float2(0.f, 0.f);
      const float4* wp = g_Q1 + c;
      float4 wA = __ldg(wp);
      wp += 128;
      const float* hp = s->H1loc;
#pragma unroll 2
      for (int p = 0; p < 64; p++) {
        float4 wB = __ldg(wp);
        wp += 128;
        float2 v[NP];
        ldrow2<NP>(hp, v);
        acc_g<NP>(v, wA.x, az);
        acc_g<NP>(v, wA.y, ar);
        ldrow2<NP>(hp + HST, v);
        acc_g<NP>(v, wA.z, az);
        acc_g<NP>(v, wA.w, ar);
        hp += 2 * HST;
        wA = wB;
      }
#pragma unroll
      for (int pl = 0; pl < NP; pl++) {
        float2 y = s->YP[t * 6 + pl];
        yv[pl] = y;
        float zx = sigma(az[pl].x + y.x * uzv + czv);
        float zy = sigma(az[pl].y + y.y * uzv + czv);
        float rx = sigma(ar[pl].x + y.x * urv + crv);
        float ry = sigma(ar[pl].y + y.y * urv + crv);
        zg[pl] = make_float2(zx, zy);
        float2 h = *reinterpret_cast<float2*>(s->H1loc + c * HST + 2 * pl);
        h1v[pl] = h;
        *reinterpret_cast<float2*>(s->XR1 + c * HST + 2 * pl) =
            make_float2(h.x * rx, h.y * ry);
      }
    }
    BARG1();
    // ---- pass 2: h-gate dot over XR1, then H1 update + peer push ----
    {
      float2 ah[NP];
#pragma unroll
      for (int p = 0; p < NP; p++) ah[p] = make_float2(0.f, 0.f);
      const float2* wp = g_Q2 + c;
      float2 wA = __ldg(wp);
      wp += 128;
      const float* hp = s->XR1;
#pragma unroll 2
      for (int p = 0; p < 64; p++) {
        float2 wB = __ldg(wp);
        wp += 128;
        float2 v[NP];
        ldrow2<NP>(hp, v);
        acc_g<NP>(v, wA.x, ah);
        ldrow2<NP>(hp + HST, v);
        acc_g<NP>(v, wA.y, ah);
        hp += 2 * HST;
        wA = wB;
      }
      // wait until layer-2 finished reading H1(t-1)
      if (t > 0) {
        mb_wait(loc_free, (unsigned)((t - 1) & 1));
        FENCE_CL();
      }
#pragma unroll
      for (int pl = 0; pl < NP; pl++) {
        float2 y = yv[pl];
        float hx = tanha(ah[pl].x + y.x * uhv + chv);
        float hy = tanha(ah[pl].y + y.y * uhv + chv);
        float2 z = zg[pl];
        float2 h = h1v[pl];
        float2 hn = make_float2(z.x * h.x + (1.f - z.x) * hx,
                                z.y * h.y + (1.f - z.y) * hy);
        *reinterpret_cast<float2*>(s->H1loc + c * HST + 2 * pl) = hn;
        stc64(peer_h1 + (unsigned)(c * HST + 2 * pl) * 4u, hn);
      }
      FENCE_CL();
      mb_arrive_loc(loc_full);
      mb_arrive_rem(peer_full);
    }
    BARG1();  // all G1 done writing H1loc before next pass1 reads it
  }
}

// ---------------- G2: layer-2 consumer (256 threads) ----------------
// tg = tid-128; c = tg&127; h = tg>>7 (k-half). pass3 row = c; pair-group = h.
template <int NP, int RANK>
__device__ float g2_run(SM* __restrict__ s, const int tg,
                        const unsigned loc_full, const unsigned loc_free,
                        const unsigned peer_free,
                        const float* __restrict__ bufA,
                        const float* __restrict__ bufB) {
  const int c = tg & 127;
  const int h = tg >> 7;  // 0 or 1
  const int PL0 = h ? 3 : 0;
  const int PL1 = h ? NP : 3;
  const float dzv = s->dzb[c], drv = s->drb[c], dhv = s->dhb[c];
  float osum = 0.f;

  for (int t = 0; t < TT; t++) {
    mb_wait(loc_full, (unsigned)(t & 1));
    FENCE_CL();
    // ---- pass 3: node mix, row c, pairs [PL0, PL1) ----
    {
      float hj[22];
      const float* rA = bufA + c * HST;
      const float* rB = bufB + c * HST;
      float4 a0 = *reinterpret_cast<const float4*>(rA);
      float4 a1 = *reinterpret_cast<const float4*>(rA + 4);
      float2 a2 = *reinterpret_cast<const float2*>(rA + 8);
      hj[0] = a0.x; hj[1] = a0.y; hj[2] = a0.z; hj[3] = a0.w;
      hj[4] = a1.x; hj[5] = a1.y; hj[6] = a1.z; hj[7] = a1.w;
      hj[8] = a2.x; hj[9] = a2.y;
      float4 b0 = *reinterpret_cast<const float4*>(rB);
      float4 b1 = *reinterpret_cast<const float4*>(rB + 4);
      float4 b2 = *reinterpret_cast<const float4*>(rB + 8);
      hj[10] = b0.x; hj[11] = b0.y; hj[12] = b0.z; hj[13] = b0.w;
      hj[14] = b1.x; hj[15] = b1.y; hj[16] = b1.z; hj[17] = b1.w;
      hj[18] = b2.x; hj[19] = b2.y; hj[20] = b2.z; hj[21] = b2.w;
#pragma unroll
      for (int pl = 0; pl < 6; pl++) {
        if (pl < PL0 || pl >= PL1) continue;
        const float2* ap = s->AP + pl * 22;
        float2 acc = make_float2(0.f, 0.f);
#pragma unroll
        for (int j = 0; j < NN; j++)
          acc = ffma2(ap[j], make_float2(hj[j], hj[j]), acc);
        *reinterpret_cast<float2*>(s->XP + c * HST + 2 * pl) = acc;
      }
    }
    FENCE_CL();
    mb_arrive_loc(loc_free);
    mb_arrive_rem(peer_free);
    BARG2();
    // ---- pass 4: fused XP·M + H2·V for z & r, k-half h ----
    {
      float2 az[NP], ar[NP];
#pragma unroll
      for (int p = 0; p < NP; p++) az[p] = ar[p] = make_float2(0.f, 0.f);
      const float4* wp = g_P4 + (h * 64) * 128 + c;
      float4 wA = __ldg(wp);
      wp += 128;
      const float* xp = s->XP + (h * 64) * HST;
      const float* hp = s->H2 + (h * 64) * HST;
#pragma unroll 2
      for (int i = 0; i < 64; i++) {
        float4 wB = __ldg(wp);
        wp += 128;
        float2 xv[NP], hv[NP];
        ldrow2<NP>(xp, xv);
        ldrow2<NP>(hp, hv);
        acc_g<NP>(xv, wA.x, az);
        acc_g<NP>(hv, wA.z, az);
        acc_g<NP>(xv, wA.y, ar);
        acc_g<NP>(hv, wA.w, ar);
        xp += HST;
        hp += HST;
        wA = wB;
      }
      float2* pz = s->PZ + c * 13 + h * 6;
      float2* pr = s->PR + c * 13 + h * 6;
#pragma unroll
      for (int pl = 0; pl < NP; pl++) {
        pz[pl] = az[pl];
        pr[pl] = ar[pl];
      }
    }
    BARG2();
    // ---- act4: gates for my pairs ----
#pragma unroll
    for (int pl = 0; pl < 6; pl++) {
      if (pl < PL0 || pl >= PL1) continue;
      float2 a0 = s->PZ[c * 13 + pl], a1 = s->PZ[c * 13 + 6 + pl];
      float2 r0 = s->PR[c * 13 + pl], r1 = s->PR[c * 13 + 6 + pl];
      float zx = sigma(a0.x + a1.x + dzv);
      float zy = sigma(a0.y + a1.y + dzv);
      float rx = sigma(r0.x + r1.x + drv);
      float ry = sigma(r0.y + r1.y + drv);
      s->ZC[c * 6 + pl] = make_float2(zx, zy);
      float2 h2 = *reinterpret_cast<float2*>(s->H2 + c * HST + 2 * pl);
      *reinterpret_cast<float2*>(s->XR2 + c * HST + 2 * pl) =
          make_float2(h2.x * rx, h2.y * ry);
    }
    BARG2();
    // ---- pass 5: fused XP·Mh + XR2·Vh, k-half h ----
    {
      float2 ah[NP];
#pragma unroll
      for (int p = 0; p < NP; p++) ah[p] = make_float2(0.f, 0.f);
      const float4* wp = g_Q5 + (h * 32) * 128 + c;
      float4 wA = __ldg(wp);
      wp += 128;
      const float* xp = s->XP + (h * 64) * HST;
      const float* rp = s->XR2 + (h * 64) * HST;
#pragma unroll 2
      for (int i = 0; i < 32; i++) {
        float4 wB = __ldg(wp);
        wp += 128;
        float2 xv[NP], rv[NP];
        ldrow2<NP>(xp, xv);
        ldrow2<NP>(rp, rv);
        acc_g<NP>(xv, wA.x, ah);
        acc_g<NP>(rv, wA.y, ah);
        ldrow2<NP>(xp + HST, xv);
        ldrow2<NP>(rp + HST, rv);
        acc_g<NP>(xv, wA.z, ah);
        acc_g<NP>(rv, wA.w, ah);
        xp += 2 * HST;
        rp += 2 * HST;
        wA = wB;
      }
      float2* pz = s->PZ + c * 13 + h * 6;
#pragma unroll
      for (int pl = 0; pl < NP; pl++) pz[pl] = ah[pl];
    }
    BARG2();
    // ---- act5: H2 update + output accumulation for my pairs ----
#pragma unroll
    for (int pl = 0; pl < 6; pl++) {
      if (pl < PL0 || pl >= PL1) continue;
      float2 a0 = s->PZ[c * 13 + pl], a1 = s->PZ[c * 13 + 6 + pl];
      float hx = tanha(a0.x + a1.x + dhv);
      float hy = tanha(a0.y + a1.y + dhv);
      float2 z = s->ZC[c * 6 + pl];
      float2 h2 = *reinterpret_cast<float2*>(s->H2 + c * HST + 2 * pl);
      float nx = z.x * h2.x + (1.f - z.x) * hx;
      float ny = z.y * h2.y + (1.f - z.y) * hy;
      *reinterpret_cast<float2*>(s->H2 + c * HST + 2 * pl) =
          make_float2(nx, ny);
      bool pad = (RANK == 1) && (pl == NP - 1);
      osum += nx + (pad ? 0.f : ny);
    }
    // next pass4 read of H2 is gated by mb_full(t+1) wait + pass3 + BARG2
  }
  return osum;
}

// ---------------- main kernel: 2-CTA cluster per batch ----------------
__global__ void __launch_bounds__(THREADS, 1) __cluster_dims__(2, 1, 1)
tgcn_main(const float* __restrict__ x, const float* __restrict__ clsw,
          const float* __restrict__ clsb, float* __restrict__ out) {
  extern __shared__ __align__(16) unsigned char smraw[];
  SM* s = reinterpret_cast<SM*>(smraw);
  const int tid = threadIdx.x;
  const int rank = blockIdx.x & 1;
  const int b = blockIdx.x >> 1;
  const int nploc = rank ? 6 : 5;
  const int gbase = rank ? 5 : 0;

  for (int i = tid; i < 128; i += THREADS) {
    s->uz[i] = g_c1[i];
    s->ur[i] = g_c1[128 + i];
    s->uh[i] = g_c1[256 + i];
    s->czb[i] = g_c1[384 + i];
    s->crb[i] = g_c1[512 + i];
    s->chb[i] = g_c1[640 + i];
    s->dzb[i] = g_c2[i];
    s->drb[i] = g_c2[128 + i];
    s->dhb[i] = g_c2[256 + i];
    s->clsw[i] = clsw[i];
  }
  for (int i = tid; i < 128 * HST; i += THREADS) {
    s->H1loc[i] = 0.f;
    s->H1rem[i] = 0.f;
    s->H2[i] = 0.f;
  }
  for (int i = tid; i < 6 * 22; i += THREADS) {
    int pl = i / 22, j = i - 22 * pl;
    float ax = 0.f, ay = 0.f;
    if (pl < nploc && j < NN) {
      int gp = gbase + pl;
      ax = g_A[(2 * gp) * NN + j];
      if (2 * gp + 1 < NN) ay = g_A[(2 * gp + 1) * NN + j];
    }
    s->AP[i] = make_float2(ax, ay);
  }
  if (tid == 0) {
    mb_init(smem_u32(&s->mb_full), 256u);
    mb_init(smem_u32(&s->mb_free), 512u);
    s->peer_sum = 0.f;
  }
  __syncthreads();

  const float* xb = x + (size_t)b * TT * NN;
  for (int i = tid; i < TT * nploc; i += THREADS) {
    int t = i / nploc, pl = i - t * nploc;
    const float2* ap = s->AP + pl * 22;
    float2 acc = make_float2(0.f, 0.f);
#pragma unroll
    for (int j = 0; j < NN; j++) {
      float xv = __ldg(xb + t * NN + j);
      acc = ffma2(ap[j], make_float2(xv, xv), acc);
    }
    s->YP[t * 6 + pl] = acc;
  }
  CLUSTER_BAR();  // peer smem + mbarriers initialized before any cluster ops

  const unsigned loc_full = smem_u32(&s->mb_full);
  const unsigned loc_free = smem_u32(&s->mb_free);
  const unsigned peer_full = mapa_u32(loc_full, (unsigned)(rank ^ 1));
  const unsigned peer_free = mapa_u32(loc_free, (unsigned)(rank ^ 1));
  const unsigned peer_h1 = mapa_u32(smem_u32(s->H1rem), (unsigned)(rank ^ 1));
  const float* bufA = rank ? s->H1rem : s->H1loc;  // nodes 0-9
  const float* bufB = rank ? s->H1loc : s->H1rem;  // nodes 10-21

  float osum = 0.f;
  if (tid < 128) {
    if (rank)
      g1_run<6, 1>(s, tid, peer_h1, loc_full, peer_full, loc_free);
    else
      g1_run<5, 0>(s, tid, peer_h1, loc_full, peer_full, loc_free);
  } else {
    if (rank)
      osum = g2_run<6, 1>(s, tid - 128, loc_full, loc_free, peer_free, bufA, bufB);
    else
      osum = g2_run<5, 0>(s, tid - 128, loc_full, loc_free, peer_free, bufA, bufB);
  }
  __syncthreads();

  float v = osum * s->clsw[tid & 127];
#pragma unroll
  for (int off = 16; off > 0; off >>= 1)
    v += __shfl_down_sync(0xffffffffu, v, off);
  if ((tid & 31) == 0) s->red[tid >> 5] = v;
  __syncthreads();
  float S = 0.f;
  if (tid == 0) {
#pragma unroll
    for (int wI = 0; wI < 12; wI++) S += s->red[wI];
    if (rank == 1) stc32(mapa_u32(smem_u32(&s->peer_sum), 0u), S);
  }
  CLUSTER_BAR();
  if (rank == 0 && tid == 0)
    out[b] = (S + s->peer_sum) * (1.0f / (TT * NN)) + clsb[0];
}

// ---------------- launch ----------------
extern "C" void kernel_launch(void* const* d_in, const int* in_sizes, int n_in,
                              void* d_out, int out_size) {
  const float* x = (const float*)d_in[0];
  const int* ei = (const int*)d_in[1];
  const float* ew = (const float*)d_in[2];
  int E = in_sizes[1] / 2;

  prep_all<<<128, 256>>>(
      E, ei, ew, (const float*)d_in[3], (const float*)d_in[4],
      (const float*)d_in[5], (const float*)d_in[6], (const float*)d_in[7],
      (const float*)d_in[8], (const float*)d_in[9], (const float*)d_in[10],
      (const float*)d_in[11], (const float*)d_in[12], (const float*)d_in[13],
      (const float*)d_in[14], (const float*)d_in[15], (const float*)d_in[16],
      (const float*)d_in[17], (const float*)d_in[18], (const float*)d_in[19],
      (const float*)d_in[20], (const float*)d_in[21], (const float*)d_in[22],
      (const float*)d_in[23], (const float*)d_in[24], (const float*)d_in[25],
      (const float*)d_in[26]);

  cudaFuncSetAttribute(tgcn_main, cudaFuncAttributeMaxDynamicSharedMemorySize,
                       (int)sizeof(SM));
  tgcn_main<<<2 * BB, THREADS, sizeof(SM)>>>(
      x, (const float*)d_in[27], (const float*)d_in[28], (float*)d_out);
}

// round 15
// speedup vs baseline: 1.1865x; 1.1865x over previous
#include <cuda_runtime.h>
#include <math.h>

#define TT 500
#define NN 21
#define BB 64
#define THREADS 384
#define HST 20     // floats per state row
#define KROWS 132  // weight rows (128 + pad; max k touched = 131)
#define SROWS 132  // state rows (pad rows stay zero)
#define PSTR 37    // float2 stride per column in partials arrays

// ---------------- device scratch (c-major, packed for 6-way k-split) --------
__device__ __align__(16) float g_A[NN * NN];
// Window w66 = i*6+ks (i=0..10, ks=0..5): ka = ks+12i, kb = ka+6.
__device__ __align__(16) float4 g_Q1[66 * 128];   // (z(ka),r(ka),z(kb),r(kb))
__device__ __align__(16) float2 g_Q2[66 * 128];   // (w1h(ka), w1h(kb))
__device__ __align__(16) float4 g_P4[KROWS * 128];// [k*128+c] = (Mz,Mr,lzw2b,lrw2b)
__device__ __align__(16) float4 g_Q5[66 * 128];   // (Mh(ka),lhw2b(ka),Mh(kb),lhw2b(kb))
__device__ __align__(16) float g_c1[6 * 128];     // uz,ur,uh,czb,crb,chb
__device__ __align__(16) float g_c2[3 * 128];     // dzb,drb,dhb

// ---------------- smem ----------------
struct SM {
  float2 YP[TT * 6];
  float2 AP[6 * 22];
  float H1loc[SROWS * HST];
  float H1rem[SROWS * HST];
  float H2[SROWS * HST];
  float XR1[SROWS * HST];
  float XP[SROWS * HST];
  float XR2[SROWS * HST];
  float2 ZC[128 * 6];
  float2 PZ[128 * PSTR + 8];  // z partials [c*PSTR + pl*6 + ks]
  float2 PR[128 * PSTR + 8];  // r partials
  float2 PH[128 * PSTR + 8];  // h partials (pass2 / pass5)
  float uz[128], ur[128], uh[128], czb[128], crb[128], chb[128];
  float dzb[128], drb[128], dhb[128], clsw[128];
  unsigned long long mb_sync;  // per-step cluster sync, 396 arrivals/phase
  float peer_sum;
  float red[12];
};

// ---------------- helpers ----------------
__device__ __forceinline__ float2 ffma2(float2 a, float2 b, float2 c) {
  float2 d;
  asm("fma.rn.f32x2 %0, %1, %2, %3;"
      : "=l"(reinterpret_cast<unsigned long long&>(d))
      : "l"(reinterpret_cast<unsigned long long&>(a)),
        "l"(reinterpret_cast<unsigned long long&>(b)),
        "l"(reinterpret_cast<unsigned long long&>(c)));
  return d;
}
__device__ __forceinline__ float tanha(float x) {
  float y;
  asm("tanh.approx.f32 %0, %1;" : "=f"(y) : "f"(x));
  return y;
}
__device__ __forceinline__ float sigma(float x) {
  return fmaf(tanha(0.5f * x), 0.5f, 0.5f);
}
__device__ __forceinline__ unsigned smem_u32(const void* p) {
  unsigned a;
  asm("{ .reg .u64 t; cvta.to.shared.u64 t, %1; cvt.u32.u64 %0, t; }"
      : "=r"(a) : "l"(p));
  return a;
}
__device__ __forceinline__ unsigned mapa_u32(unsigned a, unsigned r) {
  unsigned o;
  asm("mapa.shared::cluster.u32 %0, %1, %2;" : "=r"(o) : "r"(a), "r"(r));
  return o;
}
__device__ __forceinline__ void stc64(unsigned a, float2 v) {
  asm volatile("st.shared::cluster.b64 [%0], %1;"
               :: "r"(a), "l"(reinterpret_cast<const unsigned long long&>(v))
               : "memory");
}
__device__ __forceinline__ void stc32(unsigned a, float v) {
  asm volatile("st.shared::cluster.b32 [%0], %1;" :: "r"(a), "f"(v) : "memory");
}
#define CLUSTER_BAR()                                             \
  do {                                                            \
    asm volatile("barrier.cluster.arrive.aligned;" ::: "memory"); \
    asm volatile("barrier.cluster.wait.aligned;" ::: "memory");   \
  } while (0)
#define FENCE_CL() asm volatile("fence.acq_rel.cluster;" ::: "memory")

__device__ __forceinline__ void mb_init(unsigned a, unsigned cnt) {
  asm volatile("mbarrier.init.shared.b64 [%0], %1;" :: "r"(a), "r"(cnt)
               : "memory");
}
__device__ __forceinline__ void mb_arrive_cnt(unsigned a, unsigned cnt) {
  asm volatile("mbarrier.arrive.shared.b64 _, [%0], %1;" :: "r"(a), "r"(cnt)
               : "memory");
}
__device__ __forceinline__ void mb_arrive_rem1(unsigned a) {
  asm volatile("mbarrier.arrive.shared::cluster.b64 _, [%0];" :: "r"(a)
               : "memory");
}
__device__ __forceinline__ void mb_wait(unsigned a, unsigned par) {
  unsigned done = 0;
  do {
    asm volatile(
        "{\n\t.reg .pred p;\n\t"
        "mbarrier.try_wait.parity.acquire.cta.shared::cta.b64 p, [%1], %2;\n\t"
        "selp.b32 %0, 1, 0, p;\n\t}"
        : "=r"(done) : "r"(a), "r"(par) : "memory");
  } while (!done);
}

// ---- load one state row's node-pairs (shared by both columns) ----
template <int NP>
__device__ __forceinline__ void ldrow2(const float* __restrict__ r, float2* v) {
  float4 a = *reinterpret_cast<const float4*>(r);
  float4 b = *reinterpret_cast<const float4*>(r + 4);
  v[0] = make_float2(a.x, a.y);
  v[1] = make_float2(a.z, a.w);
  v[2] = make_float2(b.x, b.y);
  v[3] = make_float2(b.z, b.w);
  if (NP == 5) {
    float2 cq = *reinterpret_cast<const float2*>(r + 8);
    v[4] = cq;
  }
  if (NP == 6) {
    float4 cq = *reinterpret_cast<const float4*>(r + 8);
    v[4] = make_float2(cq.x, cq.y);
    v[5] = make_float2(cq.z, cq.w);
  }
}

template <int NP>
__device__ __forceinline__ void acc_g(const float2* v, float w, float2* a) {
  float2 w2 = make_float2(w, w);
#pragma unroll
  for (int p = 0; p < NP; p++) a[p] = ffma2(v[p], w2, a[p]);
}

// ---- window kernels (2 k's 6 rows apart, 2 columns) ----
template <int NP>
__device__ __forceinline__ void win1(float4 w0, float4 w1, const float* ra,
                                     const float* rb, float2* az0, float2* ar0,
                                     float2* az1, float2* ar1) {
  float2 v[NP];
  ldrow2<NP>(ra, v);
  acc_g<NP>(v, w0.x, az0);
  acc_g<NP>(v, w0.y, ar0);
  acc_g<NP>(v, w1.x, az1);
  acc_g<NP>(v, w1.y, ar1);
  ldrow2<NP>(rb, v);
  acc_g<NP>(v, w0.z, az0);
  acc_g<NP>(v, w0.w, ar0);
  acc_g<NP>(v, w1.z, az1);
  acc_g<NP>(v, w1.w, ar1);
}

template <int NP>
__device__ __forceinline__ void win2(float2 w0, float2 w1, const float* ra,
                                     const float* rb, float2* ah0, float2* ah1) {
  float2 v[NP];
  ldrow2<NP>(ra, v);
  acc_g<NP>(v, w0.x, ah0);
  acc_g<NP>(v, w1.x, ah1);
  ldrow2<NP>(rb, v);
  acc_g<NP>(v, w0.y, ah0);
  acc_g<NP>(v, w1.y, ah1);
}

template <int NP>
__device__ __forceinline__ void win4(float4 u0, float4 u1, float4 t0w,
                                     float4 t1w, const float* xa,
                                     const float* ha, const float* xb,
                                     const float* hb, float2* az0, float2* ar0,
                                     float2* az1, float2* ar1) {
  float2 xv[NP], hv[NP];
  ldrow2<NP>(xa, xv);
  ldrow2<NP>(ha, hv);
  acc_g<NP>(xv, u0.x, az0);
  acc_g<NP>(hv, u0.z, az0);
  acc_g<NP>(xv, u0.y, ar0);
  acc_g<NP>(hv, u0.w, ar0);
  acc_g<NP>(xv, u1.x, az1);
  acc_g<NP>(hv, u1.z, az1);
  acc_g<NP>(xv, u1.y, ar1);
  acc_g<NP>(hv, u1.w, ar1);
  ldrow2<NP>(xb, xv);
  ldrow2<NP>(hb, hv);
  acc_g<NP>(xv, t0w.x, az0);
  acc_g<NP>(hv, t0w.z, az0);
  acc_g<NP>(xv, t0w.y, ar0);
  acc_g<NP>(hv, t0w.w, ar0);
  acc_g<NP>(xv, t1w.x, az1);
  acc_g<NP>(hv, t1w.z, az1);
  acc_g<NP>(xv, t1w.y, ar1);
  acc_g<NP>(hv, t1w.w, ar1);
}

template <int NP>
__device__ __forceinline__ void win5(float4 w0, float4 w1, const float* xa,
                                     const float* ra_, const float* xb,
                                     const float* rb_, float2* ah0,
                                     float2* ah1) {
  float2 xv[NP], rv[NP];
  ldrow2<NP>(xa, xv);
  ldrow2<NP>(ra_, rv);
  acc_g<NP>(xv, w0.x, ah0);
  acc_g<NP>(rv, w0.y, ah0);
  acc_g<NP>(xv, w1.x, ah1);
  acc_g<NP>(rv, w1.y, ah1);
  ldrow2<NP>(xb, xv);
  ldrow2<NP>(rb_, rv);
  acc_g<NP>(xv, w0.z, ah0);
  acc_g<NP>(rv, w0.w, ah0);
  acc_g<NP>(xv, w1.z, ah1);
  acc_g<NP>(rv, w1.w, ah1);
}

// ---- partial write / read (6-way) ----
template <int NP>
__device__ __forceinline__ void wpart2(float2* P, int c0, int ks,
                                       const float2* a0, const float2* a1) {
  float2* p0 = P + c0 * PSTR + ks;
  float2* p1 = P + (c0 + 32) * PSTR + ks;
#pragma unroll
  for (int p = 0; p < NP; p++) {
    p0[p * 6] = a0[p];
    p1[p * 6] = a1[p];
  }
}
__device__ __forceinline__ float2 rpart(const float2* P, int c, int pl) {
  const float2* p = P + c * PSTR + pl * 6;
  float2 a = p[0], b = p[1], d = p[2], e = p[3], f = p[4], g = p[5];
  return make_float2(a.x + b.x + d.x + e.x + f.x + g.x,
                     a.y + b.y + d.y + e.y + f.y + g.y);
}

// ---- activations ----
__device__ __forceinline__ void act1(SM* s, int tau, int t) {
  int c = tau & 127, pl = tau >> 7;
  float2 az = rpart(s->PZ, c, pl), ar = rpart(s->PR, c, pl);
  float2 y = s->YP[t * 6 + pl];
  float uzv = s->uz[c], urv = s->ur[c], czv = s->czb[c], crv = s->crb[c];
  float zx = sigma(az.x + y.x * uzv + czv);
  float zy = sigma(az.y + y.y * uzv + czv);
  float rx = sigma(ar.x + y.x * urv + crv);
  float ry = sigma(ar.y + y.y * urv + crv);
  s->ZC[c * 6 + pl] = make_float2(zx, zy);
  float2 h = *reinterpret_cast<float2*>(s->H1loc + c * HST + 2 * pl);
  *reinterpret_cast<float2*>(s->XR1 + c * HST + 2 * pl) =
      make_float2(h.x * rx, h.y * ry);
}

__device__ __forceinline__ void act2(SM* s, int tau, int t, unsigned peer) {
  int c = tau & 127, pl = tau >> 7;
  float2 ah = rpart(s->PH, c, pl);
  float2 y = s->YP[t * 6 + pl];
  float uhv = s->uh[c], chv = s->chb[c];
  float hx = tanha(ah.x + y.x * uhv + chv);
  float hy = tanha(ah.y + y.y * uhv + chv);
  float2 z = s->ZC[c * 6 + pl];
  float2 h = *reinterpret_cast<float2*>(s->H1loc + c * HST + 2 * pl);
  float2 hn = make_float2(z.x * h.x + (1.f - z.x) * hx,
                          z.y * h.y + (1.f - z.y) * hy);
  *reinterpret_cast<float2*>(s->H1loc + c * HST + 2 * pl) = hn;
  stc64(peer + (unsigned)(c * HST + 2 * pl) * 4u, hn);
}

__device__ __forceinline__ void act4(SM* s, int tau) {
  int c = tau & 127, pl = tau >> 7;
  float2 az = rpart(s->PZ, c, pl), ar = rpart(s->PR, c, pl);
  float dzv = s->dzb[c], drv = s->drb[c];
  float zx = sigma(az.x + dzv);
  float zy = sigma(az.y + dzv);
  float rx = sigma(ar.x + drv);
  float ry = sigma(ar.y + drv);
  s->ZC[c * 6 + pl] = make_float2(zx, zy);
  float2 h = *reinterpret_cast<float2*>(s->H2 + c * HST + 2 * pl);
  *reinterpret_cast<float2*>(s->XR2 + c * HST + 2 * pl) =
      make_float2(h.x * rx, h.y * ry);
}

template <int NP, int RANK>
__device__ __forceinline__ float act5(SM* s, int tau) {
  int c = tau & 127, pl = tau >> 7;
  float2 ah = rpart(s->PH, c, pl);
  float dhv = s->dhb[c];
  float hx = tanha(ah.x + dhv);
  float hy = tanha(ah.y + dhv);
  float2 z = s->ZC[c * 6 + pl];
  float2 h = *reinterpret_cast<float2*>(s->H2 + c * HST + 2 * pl);
  float nx = z.x * h.x + (1.f - z.x) * hx;
  float ny = z.y * h.y + (1.f - z.y) * hy;
  *reinterpret_cast<float2*>(s->H2 + c * HST + 2 * pl) = make_float2(nx, ny);
  bool pad = (RANK == 1) && (pl == NP - 1);
  return nx + (pad ? 0.f : ny);
}

// ---------------- merged prep kernel ----------------
__global__ void prep_all(
    int E, const int* __restrict__ ei, const float* __restrict__ ew,
    const float* Wz1, const float* bz1, const float* lzw1, const float* lzb1,
    const float* Wr1, const float* br1, const float* lrw1, const float* lrb1,
    const float* Wh1, const float* bh1, const float* lhw1, const float* lhb1,
    const float* Wz2, const float* bz2, const float* lzw2, const float* lzb2,
    const float* Wr2, const float* br2, const float* lrw2, const float* lrb2,
    const float* Wh2, const float* bh2, const float* lhw2, const float* lhb2) {
  if (blockIdx.x == 0 && threadIdx.x == 0) {
    float deg[NN], dinv[NN];
    for (int n = 0; n < NN; n++) deg[n] = 1.0f;
    for (int e = 0; e < E; e++) deg[ei[E + e]] += ew[e];
    for (int n = 0; n < NN; n++) dinv[n] = (deg[n] > 0.f) ? rsqrtf(deg[n]) : 0.f;
    for (int i = 0; i < NN * NN; i++) g_A[i] = 0.f;
    for (int e = 0; e < E; e++) {
      int sN = ei[e], d = ei[E + e];
      g_A[d * NN + sN] += dinv[sN] * ew[e] * dinv[d];
    }
    for (int n = 0; n < NN; n++) g_A[n * NN + n] += dinv[n] * dinv[n];
  }
  int t0 = blockIdx.x * blockDim.x + threadIdx.x;
  int nt = gridDim.x * blockDim.x;

  for (int i = t0; i < 66 * 128; i += nt) {
    int c = i & 127, w66 = i >> 7;
    int ii = w66 / 6, ks = w66 - 6 * ii;
    int ka = ks + 12 * ii, kb = ka + 6;
    float z0 = lzw1[(128 + ka) * 128 + c];
    float r0 = lrw1[(128 + ka) * 128 + c];
    float q20 = lhw1[(128 + ka) * 128 + c];
    float h50 = lhw2[(128 + ka) * 128 + c];
    float m0 = 0.f;
    for (int m = 0; m < 128; m++) m0 += Wh2[ka * 128 + m] * lhw2[m * 128 + c];
    float z1 = 0, r1 = 0, q21 = 0, h51 = 0, m1 = 0;
    if (kb < 128) {
      z1 = lzw1[(128 + kb) * 128 + c];
      r1 = lrw1[(128 + kb) * 128 + c];
      q21 = lhw1[(128 + kb) * 128 + c];
      h51 = lhw2[(128 + kb) * 128 + c];
      for (int m = 0; m < 128; m++) m1 += Wh2[kb * 128 + m] * lhw2[m * 128 + c];
    }
    g_Q1[i] = make_float4(z0, r0, z1, r1);
    g_Q2[i] = make_float2(q20, q21);
    g_Q5[i] = make_float4(m0, h50, m1, h51);
  }
  for (int i = t0; i < KROWS * 128; i += nt) {
    int k = i >> 7, c = i & 127;
    if (k < 128) {
      float mz = 0.f, mr = 0.f;
      for (int m = 0; m < 128; m++) {
        mz += Wz2[k * 128 + m] * lzw2[m * 128 + c];
        mr += Wr2[k * 128 + m] * lrw2[m * 128 + c];
      }
      g_P4[i] = make_float4(mz, mr, lzw2[(128 + k) * 128 + c],
                            lrw2[(128 + k) * 128 + c]);
    } else {
      g_P4[i] = make_float4(0.f, 0.f, 0.f, 0.f);
    }
  }
  for (int c = t0; c < 128; c += nt) {
    float uz = 0, ur = 0, uh = 0, cz = 0, cr = 0, ch = 0, dz = 0, dr = 0, dh = 0;
    for (int m = 0; m < 128; m++) {
      uz += Wz1[m] * lzw1[m * 128 + c];
      ur += Wr1[m] * lrw1[m * 128 + c];
      uh += Wh1[m] * lhw1[m * 128 + c];
      cz += bz1[m] * lzw1[m * 128 + c];
      cr += br1[m] * lrw1[m * 128 + c];
      ch += bh1[m] * lhw1[m * 128 + c];
      dz += bz2[m] * lzw2[m * 128 + c];
      dr += br2[m] * lrw2[m * 128 + c];
      dh += bh2[m] * lhw2[m * 128 + c];
    }
    g_c1[0 * 128 + c] = uz;
    g_c1[1 * 128 + c] = ur;
    g_c1[2 * 128 + c] = uh;
    g_c1[3 * 128 + c] = cz + lzb1[c];
    g_c1[4 * 128 + c] = cr + lrb1[c];
    g_c1[5 * 128 + c] = ch + lhb1[c];
    g_c2[0 * 128 + c] = dz + lzb2[c];
    g_c2[1 * 128 + c] = dr + lrb2[c];
    g_c2[2 * 128 + c] = dh + lhb2[c];
  }
}

// ---------------- per-thread recurrence ----------------
// Thread: warp w, lane l. cb = w&1, ks = w>>1. Columns c0 = cb*64+l, c1 = c0+32.
template <int NP, int RANK>
__device__ float run(SM* __restrict__ s, const int c0, const int ks,
                     const int tid, const unsigned peer_h1,
                     const unsigned loc_mb, const unsigned peer_mb,
                     const float* __restrict__ bufA,
                     const float* __restrict__ bufB) {
  const int off = ks * 128 + c0;
  float osum = 0.f;
  const int t0 = tid;
  const int t1 = tid + THREADS;
  const bool has1 = (t1 < 128 * NP);
  const int k3 = tid & 127;
  const int pgrp = tid >> 7;
  const int p3a = 2 * pgrp;
  const int p3b = p3a + 1;
  const bool hasb = (p3b < NP);
  const bool lead = ((tid & 31) == 0);

  float4 w1A0 = __ldg(g_Q1 + off), w1A1 = __ldg(g_Q1 + off + 32);

  for (int t = 0; t < TT; t++) {
    {  // ---- pass 1: layer1 z & r ----
      float2 az0[NP], ar0[NP], az1[NP], ar1[NP];
#pragma unroll
      for (int p = 0; p < NP; p++) {
        az0[p] = ar0[p] = az1[p] = ar1[p] = make_float2(0.f, 0.f);
      }
      const float4* wpa = g_Q1 + off + 768;
      const float* hp = s->H1loc + ks * HST;
      float4 wA0 = w1A0, wA1 = w1A1, wB0, wB1;
#pragma unroll 1
      for (int j = 0; j < 5; j++) {
        wB0 = __ldg(wpa); wB1 = __ldg(wpa + 32); wpa += 768;
        win1<NP>(wA0, wA1, hp, hp + 6 * HST, az0, ar0, az1, ar1);
        hp += 12 * HST;
        wA0 = __ldg(wpa); wA1 = __ldg(wpa + 32); wpa += 768;
        win1<NP>(wB0, wB1, hp, hp + 6 * HST, az0, ar0, az1, ar1);
        hp += 12 * HST;
      }
      win1<NP>(wA0, wA1, hp, hp + 6 * HST, az0, ar0, az1, ar1);
      wpart2<NP>(s->PZ, c0, ks, az0, az1);
      wpart2<NP>(s->PR, c0, ks, ar0, ar1);
    }
    float2 w2A0 = __ldg(g_Q2 + off), w2A1 = __ldg(g_Q2 + off + 32);
    __syncthreads();  // B1
    act1(s, t0, t);
    if (has1) act1(s, t1, t);
    __syncthreads();  // B2
    {  // ---- pass 2: layer1 h-gate ----
      float2 ah0[NP], ah1[NP];
#pragma unroll
      for (int p = 0; p < NP; p++) ah0[p] = ah1[p] = make_float2(0.f, 0.f);
      const float2* wpa = g_Q2 + off + 768;
      const float* hp = s->XR1 + ks * HST;
      float2 wA0 = w2A0, wA1 = w2A1, wB0, wB1;
#pragma unroll 1
      for (int j = 0; j < 5; j++) {
        wB0 = __ldg(wpa); wB1 = __ldg(wpa + 32); wpa += 768;
        win2<NP>(wA0, wA1, hp, hp + 6 * HST, ah0, ah1);
        hp += 12 * HST;
        wA0 = __ldg(wpa); wA1 = __ldg(wpa + 32); wpa += 768;
        win2<NP>(wB0, wB1, hp, hp + 6 * HST, ah0, ah1);
        hp += 12 * HST;
      }
      win2<NP>(wA0, wA1, hp, hp + 6 * HST, ah0, ah1);
      wpart2<NP>(s->PH, c0, ks, ah0, ah1);
    }
    float4 w4u0 = __ldg(g_P4 + off), w4u1 = __ldg(g_P4 + off + 32);
    float4 w4t0 = __ldg(g_P4 + off + 768), w4t1 = __ldg(g_P4 + off + 800);
    __syncthreads();  // B3
    act2(s, t0, t, peer_h1);
    if (has1) act2(s, t1, t, peer_h1);
    // ---- B4: cluster-wide H1 handoff via parity mbarrier ----
    FENCE_CL();
    __syncwarp(0xffffffffu);
    if (lead) {
      mb_arrive_cnt(loc_mb, 32u);
      mb_arrive_rem1(peer_mb);
    }
    mb_wait(loc_mb, (unsigned)(t & 1));
    {  // ---- pass 3: node mix (row k3, pairs p3a/p3b) ----
      const float* rA = bufA + k3 * HST;
      const float* rB = bufB + k3 * HST;
      float hj[22];
      float4 a0 = *reinterpret_cast<const float4*>(rA);
      float4 a1 = *reinterpret_cast<const float4*>(rA + 4);
      float2 a2 = *reinterpret_cast<const float2*>(rA + 8);
      hj[0] = a0.x; hj[1] = a0.y; hj[2] = a0.z; hj[3] = a0.w;
      hj[4] = a1.x; hj[5] = a1.y; hj[6] = a1.z; hj[7] = a1.w;
      hj[8] = a2.x; hj[9] = a2.y;
      float4 b0 = *reinterpret_cast<const float4*>(rB);
      float4 b1 = *reinterpret_cast<const float4*>(rB + 4);
      float4 b2 = *reinterpret_cast<const float4*>(rB + 8);
      hj[10] = b0.x; hj[11] = b0.y; hj[12] = b0.z; hj[13] = b0.w;
      hj[14] = b1.x; hj[15] = b1.y; hj[16] = b1.z; hj[17] = b1.w;
      hj[18] = b2.x; hj[19] = b2.y; hj[20] = b2.z; hj[21] = b2.w;
      {
        const float2* ap = s->AP + p3a * 22;
        float2 acc = make_float2(0.f, 0.f);
#pragma unroll
        for (int j = 0; j < NN; j++)
          acc = ffma2(ap[j], make_float2(hj[j], hj[j]), acc);
        *reinterpret_cast<float2*>(s->XP + k3 * HST + 2 * p3a) = acc;
      }
      if (hasb) {
        const float2* ap = s->AP + p3b * 22;
        float2 acc = make_float2(0.f, 0.f);
#pragma unroll
        for (int j = 0; j < NN; j++)
          acc = ffma2(ap[j], make_float2(hj[j], hj[j]), acc);
        *reinterpret_cast<float2*>(s->XP + k3 * HST + 2 * p3b) = acc;
      }
    }
    __syncthreads();  // B5
    {  // ---- pass 4: layer2 z & r (fused XP·M + H2·W) ----
      float2 az0[NP], ar0[NP], az1[NP], ar1[NP];
#pragma unroll
      for (int p = 0; p < NP; p++) {
        az0[p] = ar0[p] = az1[p] = ar1[p] = make_float2(0.f, 0.f);
      }
      const float4* wpa = g_P4 + off + 1536;
      const float* xp = s->XP + ks * HST;
      const float* hp = s->H2 + ks * HST;
      float4 u0 = w4u0, u1 = w4u1, v0 = w4t0, v1 = w4t1;
      float4 n0, n1, m0, m1;
#pragma unroll 1
      for (int j = 0; j < 5; j++) {
        n0 = __ldg(wpa); n1 = __ldg(wpa + 32);
        m0 = __ldg(wpa + 768); m1 = __ldg(wpa + 800); wpa += 1536;
        win4<NP>(u0, u1, v0, v1, xp, hp, xp + 6 * HST, hp + 6 * HST, az0, ar0,
                 az1, ar1);
        xp += 12 * HST; hp += 12 * HST;
        u0 = __ldg(wpa); u1 = __ldg(wpa + 32);
        v0 = __ldg(wpa + 768); v1 = __ldg(wpa + 800); wpa += 1536;
        win4<NP>(n0, n1, m0, m1, xp, hp, xp + 6 * HST, hp + 6 * HST, az0, ar0,
                 az1, ar1);
        xp += 12 * HST; hp += 12 * HST;
      }
      win4<NP>(u0, u1, v0, v1, xp, hp, xp + 6 * HST, hp + 6 * HST, az0, ar0,
               az1, ar1);
      wpart2<NP>(s->PZ, c0, ks, az0, az1);
      wpart2<NP>(s->PR, c0, ks, ar0, ar1);
    }
    float4 w5A0 = __ldg(g_Q5 + off), w5A1 = __ldg(g_Q5 + off + 32);
    __syncthreads();  // B6
    act4(s, t0);
    if (has1) act4(s, t1);
    __syncthreads();  // B7
    {  // ---- pass 5: layer2 h-gate ----
      float2 ah0[NP], ah1[NP];
#pragma unroll
      for (int p = 0; p < NP; p++) ah0[p] = ah1[p] = make_float2(0.f, 0.f);
      const float4* wpa = g_Q5 + off + 768;
      const float* xp = s->XP + ks * HST;
      const float* rp = s->XR2 + ks * HST;
      float4 wA0 = w5A0, wA1 = w5A1, wB0, wB1;
#pragma unroll 1
      for (int j = 0; j < 5; j++) {
        wB0 = __ldg(wpa); wB1 = __ldg(wpa + 32); wpa += 768;
        win5<NP>(wA0, wA1, xp, rp, xp + 6 * HST, rp + 6 * HST, ah0, ah1);
        xp += 12 * HST; rp += 12 * HST;
        wA0 = __ldg(wpa); wA1 = __ldg(wpa + 32); wpa += 768;
        win5<NP>(wB0, wB1, xp, rp, xp + 6 * HST, rp + 6 * HST, ah0, ah1);
        xp += 12 * HST; rp += 12 * HST;
      }
      win5<NP>(wA0, wA1, xp, rp, xp + 6 * HST, rp + 6 * HST, ah0, ah1);
      wpart2<NP>(s->PH, c0, ks, ah0, ah1);
    }
    w1A0 = __ldg(g_Q1 + off);
    w1A1 = __ldg(g_Q1 + off + 32);
    __syncthreads();  // B8
    osum += act5<NP, RANK>(s, t0);
    if (has1) osum += act5<NP, RANK>(s, t1);
    // B9 removed: act5 reads PH/ZC/H2 only; pass1(t+1) writes PZ/PR and
    // reads H1loc — disjoint. Next PH write (pass2(t+1)) is gated by B3(t+1).
  }
  return osum;
}

// ---------------- main kernel: 2-CTA cluster per batch ----------------
__global__ void __launch_bounds__(THREADS, 1) __cluster_dims__(2, 1, 1)
tgcn_main(const float* __restrict__ x, const float* __restrict__ clsw,
          const float* __restrict__ clsb, float* __restrict__ out) {
  extern __shared__ __align__(16) unsigned char smraw[];
  SM* s = reinterpret_cast<SM*>(smraw);
  const int tid = threadIdx.x;
  const int rank = blockIdx.x & 1;
  const int b = blockIdx.x >> 1;
  const int w = tid >> 5;
  const int l = tid & 31;
  const int c0 = (w & 1) * 64 + l;
  const int ks = w >> 1;
  const int nploc = rank ? 6 : 5;
  const int gbase = rank ? 5 : 0;

  for (int i = tid; i < 128; i += THREADS) {
    s->uz[i] = g_c1[i];
    s->ur[i] = g_c1[128 + i];
    s->uh[i] = g_c1[256 + i];
    s->czb[i] = g_c1[384 + i];
    s->crb[i] = g_c1[512 + i];
    s->chb[i] = g_c1[640 + i];
    s->dzb[i] = g_c2[i];
    s->drb[i] = g_c2[128 + i];
    s->dhb[i] = g_c2[256 + i];
    s->clsw[i] = clsw[i];
  }
  for (int i = tid; i < SROWS * HST; i += THREADS) {
    s->H1loc[i] = 0.f;
    s->H1rem[i] = 0.f;
    s->H2[i] = 0.f;
    s->XR1[i] = 0.f;
    s->XP[i] = 0.f;
    s->XR2[i] = 0.f;
  }
  for (int i = tid; i < 6 * 22; i += THREADS) {
    int pl = i / 22, j = i - 22 * pl;
    float ax = 0.f, ay = 0.f;
    if (pl < nploc && j < NN) {
      int gp = gbase + pl;
      ax = g_A[(2 * gp) * NN + j];
      if (2 * gp + 1 < NN) ay = g_A[(2 * gp + 1) * NN + j];
    }
    s->AP[i] = make_float2(ax, ay);
  }
  if (tid == 0) {
    mb_init(smem_u32(&s->mb_sync), 396u);  // 12 warps*32 local + 12 remote
    s->peer_sum = 0.f;
  }
  __syncthreads();

  const float* xb = x + (size_t)b * TT * NN;
  for (int i = tid; i < TT * nploc; i += THREADS) {
    int t = i / nploc, pl = i - t * nploc;
    const float2* ap = s->AP + pl * 22;
    float2 acc = make_float2(0.f, 0.f);
#pragma unroll
    for (int j = 0; j < NN; j++) {
      float xv = __ldg(xb + t * NN + j);
      acc = ffma2(ap[j], make_float2(xv, xv), acc);
    }
    s->YP[t * 6 + pl] = acc;
  }
  CLUSTER_BAR();  // peer smem + mbarrier init visible before any cluster ops

  const unsigned loc_mb = smem_u32(&s->mb_sync);
  const unsigned peer_mb = mapa_u32(loc_mb, (unsigned)(rank ^ 1));
  const unsigned peer_h1 = mapa_u32(smem_u32(s->H1rem), (unsigned)(rank ^ 1));
  const float* bufA = rank ? s->H1rem : s->H1loc;
  const float* bufB = rank ? s->H1loc : s->H1rem;

  float osum;
  if (rank)
    osum = run<6, 1>(s, c0, ks, tid, peer_h1, loc_mb, peer_mb, bufA, bufB);
  else
    osum = run<5, 0>(s, c0, ks, tid, peer_h1, loc_mb, peer_mb, bufA, bufB);

  __syncthreads();
  float v = osum * s->clsw[tid & 127];
#pragma unroll
  for (int off = 16; off > 0; off >>= 1)
    v += __shfl_down_sync(0xffffffffu, v, off);
  if ((tid & 31) == 0) s->red[tid >> 5] = v;
  __syncthreads();
  float S = 0.f;
  if (tid == 0) {
#pragma unroll
    for (int wI = 0; wI < 12; wI++) S += s->red[wI];
    if (rank == 1) stc32(mapa_u32(smem_u32(&s->peer_sum), 0u), S);
  }
  CLUSTER_BAR();
  if (rank == 0 && tid == 0)
    out[b] = (S + s->peer_sum) * (1.0f / (TT * NN)) + clsb[0];
}

// ---------------- launch ----------------
extern "C" void kernel_launch(void* const* d_in, const int* in_sizes, int n_in,
                              void* d_out, int out_size) {
  const float* x = (const float*)d_in[0];
  const int* ei = (const int*)d_in[1];
  const float* ew = (const float*)d_in[2];
  int E = in_sizes[1] / 2;

  prep_all<<<128, 256>>>(
      E, ei, ew, (const float*)d_in[3], (const float*)d_in[4],
      (const float*)d_in[5], (const float*)d_in[6], (const float*)d_in[7],
      (const float*)d_in[8], (const float*)d_in[9], (const float*)d_in[10],
      (const float*)d_in[11], (const float*)d_in[12], (const float*)d_in[13],
      (const float*)d_in[14], (const float*)d_in[15], (const float*)d_in[16],
      (const float*)d_in[17], (const float*)d_in[18], (const float*)d_in[19],
      (const float*)d_in[20], (const float*)d_in[21], (const float*)d_in[22],
      (const float*)d_in[23], (const float*)d_in[24], (const float*)d_in[25],
      (const float*)d_in[26]);

  cudaFuncSetAttribute(tgcn_main, cudaFuncAttributeMaxDynamicSharedMemorySize,
                       (int)sizeof(SM));
  tgcn_main<<<2 * BB, THREADS, sizeof(SM)>>>(
      x, (const float*)d_in[27], (const float*)d_in[28], (float*)d_out);
}

// round 16
// speedup vs baseline: 1.2201x; 1.0283x over previous
#include <cuda_runtime.h>
#include <math.h>

#define TT 500
#define NN 21
#define BB 64
#define THREADS 384
#define HST 20     // floats per state row
#define KROWS 132  // weight rows (128 + pad; max k touched = 131)
#define SROWS 132  // state rows (pad rows stay zero)
#define PSTR 37    // float2 stride per column in partials arrays

// ---------------- device scratch (c-major, packed for 6-way k-split) --------
__device__ __align__(16) float g_A[NN * NN];
// Window w66 = i*6+ks (i=0..10, ks=0..5): ka = ks+12i, kb = ka+6.
__device__ __align__(16) float4 g_Q1[66 * 128];   // (z(ka),r(ka),z(kb),r(kb))
__device__ __align__(16) float2 g_Q2[66 * 128];   // (w1h(ka), w1h(kb))
__device__ __align__(16) float4 g_P4[KROWS * 128];// [k*128+c] = (Mz,Mr,lzw2b,lrw2b)
__device__ __align__(16) float4 g_Q5[66 * 128];   // (Mh(ka),lhw2b(ka),Mh(kb),lhw2b(kb))
__device__ __align__(16) float g_c1[6 * 128];     // uz,ur,uh,czb,crb,chb
__device__ __align__(16) float g_c2[3 * 128];     // dzb,drb,dhb

// ---------------- smem ----------------
struct SM {
  float2 YP[TT * 6];
  float2 AP[6 * 22];
  float H1loc[SROWS * HST];
  float H1rem[SROWS * HST];
  float H2[SROWS * HST];
  float XR1[SROWS * HST];
  float XP[SROWS * HST];
  float XR2[SROWS * HST];
  float2 ZC[128 * 6];
  float2 PZ[128 * PSTR + 8];  // z partials [c*PSTR + pl*6 + ks]
  float2 PR[128 * PSTR + 8];  // r partials
  float2 PH[128 * PSTR + 8];  // h partials (pass2 / pass5)
  float uz[128], ur[128], uh[128], czb[128], crb[128], chb[128];
  float dzb[128], drb[128], dhb[128], clsw[128];
  float peer_sum;
  float red[12];
};

// ---------------- helpers ----------------
__device__ __forceinline__ float2 ffma2(float2 a, float2 b, float2 c) {
  float2 d;
  asm("fma.rn.f32x2 %0, %1, %2, %3;"
      : "=l"(reinterpret_cast<unsigned long long&>(d))
      : "l"(reinterpret_cast<unsigned long long&>(a)),
        "l"(reinterpret_cast<unsigned long long&>(b)),
        "l"(reinterpret_cast<unsigned long long&>(c)));
  return d;
}
__device__ __forceinline__ float tanha(float x) {
  float y;
  asm("tanh.approx.f32 %0, %1;" : "=f"(y) : "f"(x));
  return y;
}
__device__ __forceinline__ float sigma(float x) {
  return fmaf(tanha(0.5f * x), 0.5f, 0.5f);
}
__device__ __forceinline__ unsigned smem_u32(const void* p) {
  unsigned a;
  asm("{ .reg .u64 t; cvta.to.shared.u64 t, %1; cvt.u32.u64 %0, t; }"
      : "=r"(a) : "l"(p));
  return a;
}
__device__ __forceinline__ unsigned mapa_u32(unsigned a, unsigned r) {
  unsigned o;
  asm("mapa.shared::cluster.u32 %0, %1, %2;" : "=r"(o) : "r"(a), "r"(r));
  return o;
}
__device__ __forceinline__ void stc64(unsigned a, float2 v) {
  asm volatile("st.shared::cluster.b64 [%0], %1;"
               :: "r"(a), "l"(reinterpret_cast<const unsigned long long&>(v))
               : "memory");
}
__device__ __forceinline__ void stc32(unsigned a, float v) {
  asm volatile("st.shared::cluster.b32 [%0], %1;" :: "r"(a), "f"(v) : "memory");
}
#define CLUSTER_BAR()                                             \
  do {                                                            \
    asm volatile("barrier.cluster.arrive.aligned;" ::: "memory"); \
    asm volatile("barrier.cluster.wait.aligned;" ::: "memory");   \
  } while (0)

// ---- load one state row's node-pairs (shared by both columns) ----
template <int NP>
__device__ __forceinline__ void ldrow2(const float* __restrict__ r, float2* v) {
  float4 a = *reinterpret_cast<const float4*>(r);
  float4 b = *reinterpret_cast<const float4*>(r + 4);
  v[0] = make_float2(a.x, a.y);
  v[1] = make_float2(a.z, a.w);
  v[2] = make_float2(b.x, b.y);
  v[3] = make_float2(b.z, b.w);
  if (NP == 5) {
    float2 cq = *reinterpret_cast<const float2*>(r + 8);
    v[4] = cq;
  }
  if (NP == 6) {
    float4 cq = *reinterpret_cast<const float4*>(r + 8);
    v[4] = make_float2(cq.x, cq.y);
    v[5] = make_float2(cq.z, cq.w);
  }
}

template <int NP>
__device__ __forceinline__ void acc_g(const float2* v, float w, float2* a) {
  float2 w2 = make_float2(w, w);
#pragma unroll
  for (int p = 0; p < NP; p++) a[p] = ffma2(v[p], w2, a[p]);
}

// ---- window kernels (2 k's 6 rows apart, 2 columns) ----
template <int NP>
__device__ __forceinline__ void win1(float4 w0, float4 w1, const float* ra,
                                     const float* rb, float2* az0, float2* ar0,
                                     float2* az1, float2* ar1) {
  float2 v[NP];
  ldrow2<NP>(ra, v);
  acc_g<NP>(v, w0.x, az0);
  acc_g<NP>(v, w0.y, ar0);
  acc_g<NP>(v, w1.x, az1);
  acc_g<NP>(v, w1.y, ar1);
  ldrow2<NP>(rb, v);
  acc_g<NP>(v, w0.z, az0);
  acc_g<NP>(v, w0.w, ar0);
  acc_g<NP>(v, w1.z, az1);
  acc_g<NP>(v, w1.w, ar1);
}

template <int NP>
__device__ __forceinline__ void win2(float2 w0, float2 w1, const float* ra,
                                     const float* rb, float2* ah0, float2* ah1) {
  float2 v[NP];
  ldrow2<NP>(ra, v);
  acc_g<NP>(v, w0.x, ah0);
  acc_g<NP>(v, w1.x, ah1);
  ldrow2<NP>(rb, v);
  acc_g<NP>(v, w0.y, ah0);
  acc_g<NP>(v, w1.y, ah1);
}

template <int NP>
__device__ __forceinline__ void win4(float4 u0, float4 u1, float4 t0w,
                                     float4 t1w, const float* xa,
                                     const float* ha, const float* xb,
                                     const float* hb, float2* az0, float2* ar0,
                                     float2* az1, float2* ar1) {
  float2 xv[NP], hv[NP];
  ldrow2<NP>(xa, xv);
  ldrow2<NP>(ha, hv);
  acc_g<NP>(xv, u0.x, az0);
  acc_g<NP>(hv, u0.z, az0);
  acc_g<NP>(xv, u0.y, ar0);
  acc_g<NP>(hv, u0.w, ar0);
  acc_g<NP>(xv, u1.x, az1);
  acc_g<NP>(hv, u1.z, az1);
  acc_g<NP>(xv, u1.y, ar1);
  acc_g<NP>(hv, u1.w, ar1);
  ldrow2<NP>(xb, xv);
  ldrow2<NP>(hb, hv);
  acc_g<NP>(xv, t0w.x, az0);
  acc_g<NP>(hv, t0w.z, az0);
  acc_g<NP>(xv, t0w.y, ar0);
  acc_g<NP>(hv, t0w.w, ar0);
  acc_g<NP>(xv, t1w.x, az1);
  acc_g<NP>(hv, t1w.z, az1);
  acc_g<NP>(xv, t1w.y, ar1);
  acc_g<NP>(hv, t1w.w, ar1);
}

template <int NP>
__device__ __forceinline__ void win5(float4 w0, float4 w1, const float* xa,
                                     const float* ra_, const float* xb,
                                     const float* rb_, float2* ah0,
                                     float2* ah1) {
  float2 xv[NP], rv[NP];
  ldrow2<NP>(xa, xv);
  ldrow2<NP>(ra_, rv);
  acc_g<NP>(xv, w0.x, ah0);
  acc_g<NP>(rv, w0.y, ah0);
  acc_g<NP>(xv, w1.x, ah1);
  acc_g<NP>(rv, w1.y, ah1);
  ldrow2<NP>(xb, xv);
  ldrow2<NP>(rb_, rv);
  acc_g<NP>(xv, w0.z, ah0);
  acc_g<NP>(rv, w0.w, ah0);
  acc_g<NP>(xv, w1.z, ah1);
  acc_g<NP>(rv, w1.w, ah1);
}

// ---- partial write / read (6-way) ----
template <int NP>
__device__ __forceinline__ void wpart2(float2* P, int c0, int ks,
                                       const float2* a0, const float2* a1) {
  float2* p0 = P + c0 * PSTR + ks;
  float2* p1 = P + (c0 + 32) * PSTR + ks;
#pragma unroll
  for (int p = 0; p < NP; p++) {
    p0[p * 6] = a0[p];
    p1[p * 6] = a1[p];
  }
}
__device__ __forceinline__ float2 rpart(const float2* P, int c, int pl) {
  const float2* p = P + c * PSTR + pl * 6;
  float2 a = p[0], b = p[1], d = p[2], e = p[3], f = p[4], g = p[5];
  return make_float2(a.x + b.x + d.x + e.x + f.x + g.x,
                     a.y + b.y + d.y + e.y + f.y + g.y);
}

// ---- activations ----
__device__ __forceinline__ void act1(SM* s, int tau, int t) {
  int c = tau & 127, pl = tau >> 7;
  float2 az = rpart(s->PZ, c, pl), ar = rpart(s->PR, c, pl);
  float2 y = s->YP[t * 6 + pl];
  float uzv = s->uz[c], urv = s->ur[c], czv = s->czb[c], crv = s->crb[c];
  float zx = sigma(az.x + y.x * uzv + czv);
  float zy = sigma(az.y + y.y * uzv + czv);
  float rx = sigma(ar.x + y.x * urv + crv);
  float ry = sigma(ar.y + y.y * urv + crv);
  s->ZC[c * 6 + pl] = make_float2(zx, zy);
  float2 h = *reinterpret_cast<float2*>(s->H1loc + c * HST + 2 * pl);
  *reinterpret_cast<float2*>(s->XR1 + c * HST + 2 * pl) =
      make_float2(h.x * rx, h.y * ry);
}

__device__ __forceinline__ void act2(SM* s, int tau, int t, unsigned peer) {
  int c = tau & 127, pl = tau >> 7;
  float2 ah = rpart(s->PH, c, pl);
  float2 y = s->YP[t * 6 + pl];
  float uhv = s->uh[c], chv = s->chb[c];
  float hx = tanha(ah.x + y.x * uhv + chv);
  float hy = tanha(ah.y + y.y * uhv + chv);
  float2 z = s->ZC[c * 6 + pl];
  float2 h = *reinterpret_cast<float2*>(s->H1loc + c * HST + 2 * pl);
  float2 hn = make_float2(z.x * h.x + (1.f - z.x) * hx,
                          z.y * h.y + (1.f - z.y) * hy);
  *reinterpret_cast<float2*>(s->H1loc + c * HST + 2 * pl) = hn;
  stc64(peer + (unsigned)(c * HST + 2 * pl) * 4u, hn);
}

__device__ __forceinline__ void act4(SM* s, int tau) {
  int c = tau & 127, pl = tau >> 7;
  float2 az = rpart(s->PZ, c, pl), ar = rpart(s->PR, c, pl);
  float dzv = s->dzb[c], drv = s->drb[c];
  float zx = sigma(az.x + dzv);
  float zy = sigma(az.y + dzv);
  float rx = sigma(ar.x + drv);
  float ry = sigma(ar.y + drv);
  s->ZC[c * 6 + pl] = make_float2(zx, zy);
  float2 h = *reinterpret_cast<float2*>(s->H2 + c * HST + 2 * pl);
  *reinterpret_cast<float2*>(s->XR2 + c * HST + 2 * pl) =
      make_float2(h.x * rx, h.y * ry);
}

template <int NP, int RANK>
__device__ __forceinline__ float act5(SM* s, int tau) {
  int c = tau & 127, pl = tau >> 7;
  float2 ah = rpart(s->PH, c, pl);
  float dhv = s->dhb[c];
  float hx = tanha(ah.x + dhv);
  float hy = tanha(ah.y + dhv);
  float2 z = s->ZC[c * 6 + pl];
  float2 h = *reinterpret_cast<float2*>(s->H2 + c * HST + 2 * pl);
  float nx = z.x * h.x + (1.f - z.x) * hx;
  float ny = z.y * h.y + (1.f - z.y) * hy;
  *reinterpret_cast<float2*>(s->H2 + c * HST + 2 * pl) = make_float2(nx, ny);
  bool pad = (RANK == 1) && (pl == NP - 1);
  return nx + (pad ? 0.f : ny);
}

// ---------------- merged prep kernel ----------------
__global__ void prep_all(
    int E, const int* __restrict__ ei, const float* __restrict__ ew,
    const float* Wz1, const float* bz1, const float* lzw1, const float* lzb1,
    const float* Wr1, const float* br1, const float* lrw1, const float* lrb1,
    const float* Wh1, const float* bh1, const float* lhw1, const float* lhb1,
    const float* Wz2, const float* bz2, const float* lzw2, const float* lzb2,
    const float* Wr2, const float* br2, const float* lrw2, const float* lrb2,
    const float* Wh2, const float* bh2, const float* lhw2, const float* lhb2) {
  if (blockIdx.x == 0 && threadIdx.x == 0) {
    float deg[NN], dinv[NN];
    for (int n = 0; n < NN; n++) deg[n] = 1.0f;
    for (int e = 0; e < E; e++) deg[ei[E + e]] += ew[e];
    for (int n = 0; n < NN; n++) dinv[n] = (deg[n] > 0.f) ? rsqrtf(deg[n]) : 0.f;
    for (int i = 0; i < NN * NN; i++) g_A[i] = 0.f;
    for (int e = 0; e < E; e++) {
      int sN = ei[e], d = ei[E + e];
      g_A[d * NN + sN] += dinv[sN] * ew[e] * dinv[d];
    }
    for (int n = 0; n < NN; n++) g_A[n * NN + n] += dinv[n] * dinv[n];
  }
  int t0 = blockIdx.x * blockDim.x + threadIdx.x;
  int nt = gridDim.x * blockDim.x;

  for (int i = t0; i < 66 * 128; i += nt) {
    int c = i & 127, w66 = i >> 7;
    int ii = w66 / 6, ks = w66 - 6 * ii;
    int ka = ks + 12 * ii, kb = ka + 6;
    float z0 = lzw1[(128 + ka) * 128 + c];
    float r0 = lrw1[(128 + ka) * 128 + c];
    float q20 = lhw1[(128 + ka) * 128 + c];
    float h50 = lhw2[(128 + ka) * 128 + c];
    float m0 = 0.f;
    for (int m = 0; m < 128; m++) m0 += Wh2[ka * 128 + m] * lhw2[m * 128 + c];
    float z1 = 0, r1 = 0, q21 = 0, h51 = 0, m1 = 0;
    if (kb < 128) {
      z1 = lzw1[(128 + kb) * 128 + c];
      r1 = lrw1[(128 + kb) * 128 + c];
      q21 = lhw1[(128 + kb) * 128 + c];
      h51 = lhw2[(128 + kb) * 128 + c];
      for (int m = 0; m < 128; m++) m1 += Wh2[kb * 128 + m] * lhw2[m * 128 + c];
    }
    g_Q1[i] = make_float4(z0, r0, z1, r1);
    g_Q2[i] = make_float2(q20, q21);
    g_Q5[i] = make_float4(m0, h50, m1, h51);
  }
  for (int i = t0; i < KROWS * 128; i += nt) {
    int k = i >> 7, c = i & 127;
    if (k < 128) {
      float mz = 0.f, mr = 0.f;
      for (int m = 0; m < 128; m++) {
        mz += Wz2[k * 128 + m] * lzw2[m * 128 + c];
        mr += Wr2[k * 128 + m] * lrw2[m * 128 + c];
      }
      g_P4[i] = make_float4(mz, mr, lzw2[(128 + k) * 128 + c],
                            lrw2[(128 + k) * 128 + c]);
    } else {
      g_P4[i] = make_float4(0.f, 0.f, 0.f, 0.f);
    }
  }
  for (int c = t0; c < 128; c += nt) {
    float uz = 0, ur = 0, uh = 0, cz = 0, cr = 0, ch = 0, dz = 0, dr = 0, dh = 0;
    for (int m = 0; m < 128; m++) {
      uz += Wz1[m] * lzw1[m * 128 + c];
      ur += Wr1[m] * lrw1[m * 128 + c];
      uh += Wh1[m] * lhw1[m * 128 + c];
      cz += bz1[m] * lzw1[m * 128 + c];
      cr += br1[m] * lrw1[m * 128 + c];
      ch += bh1[m] * lhw1[m * 128 + c];
      dz += bz2[m] * lzw2[m * 128 + c];
      dr += br2[m] * lrw2[m * 128 + c];
      dh += bh2[m] * lhw2[m * 128 + c];
    }
    g_c1[0 * 128 + c] = uz;
    g_c1[1 * 128 + c] = ur;
    g_c1[2 * 128 + c] = uh;
    g_c1[3 * 128 + c] = cz + lzb1[c];
    g_c1[4 * 128 + c] = cr + lrb1[c];
    g_c1[5 * 128 + c] = ch + lhb1[c];
    g_c2[0 * 128 + c] = dz + lzb2[c];
    g_c2[1 * 128 + c] = dr + lrb2[c];
    g_c2[2 * 128 + c] = dh + lhb2[c];
  }
}

// ---------------- per-thread recurrence ----------------
// Thread: warp w, lane l. cb = w&1, ks = w>>1. Columns c0 = cb*64+l, c1 = c0+32.
template <int NP, int RANK>
__device__ float run(SM* __restrict__ s, const int c0, const int ks,
                     const int tid, const unsigned peer_h1,
                     const float* __restrict__ bufA,
                     const float* __restrict__ bufB) {
  const int off = ks * 128 + c0;
  float osum = 0.f;
  const int t0 = tid;
  const int t1 = tid + THREADS;
  const bool has1 = (t1 < 128 * NP);
  const int k3 = tid & 127;
  const int pgrp = tid >> 7;
  const int p3a = 2 * pgrp;
  const int p3b = p3a + 1;
  const bool hasb = (p3b < NP);

  float4 w1A0 = __ldg(g_Q1 + off), w1A1 = __ldg(g_Q1 + off + 32);

  for (int t = 0; t < TT; t++) {
    {  // ---- pass 1: layer1 z & r ----
      float2 az0[NP], ar0[NP], az1[NP], ar1[NP];
#pragma unroll
      for (int p = 0; p < NP; p++) {
        az0[p] = ar0[p] = az1[p] = ar1[p] = make_float2(0.f, 0.f);
      }
      const float4* wpa = g_Q1 + off + 768;
      const float* hp = s->H1loc + ks * HST;
      float4 wA0 = w1A0, wA1 = w1A1, wB0, wB1;
#pragma unroll 1
      for (int j = 0; j < 5; j++) {
        wB0 = __ldg(wpa); wB1 = __ldg(wpa + 32); wpa += 768;
        win1<NP>(wA0, wA1, hp, hp + 6 * HST, az0, ar0, az1, ar1);
        hp += 12 * HST;
        wA0 = __ldg(wpa); wA1 = __ldg(wpa + 32); wpa += 768;
        win1<NP>(wB0, wB1, hp, hp + 6 * HST, az0, ar0, az1, ar1);
        hp += 12 * HST;
      }
      win1<NP>(wA0, wA1, hp, hp + 6 * HST, az0, ar0, az1, ar1);
      wpart2<NP>(s->PZ, c0, ks, az0, az1);
      wpart2<NP>(s->PR, c0, ks, ar0, ar1);
    }
    float2 w2A0 = __ldg(g_Q2 + off), w2A1 = __ldg(g_Q2 + off + 32);
    __syncthreads();  // B1
    act1(s, t0, t);
    if (has1) act1(s, t1, t);
    __syncthreads();  // B2
    {  // ---- pass 2: layer1 h-gate ----
      float2 ah0[NP], ah1[NP];
#pragma unroll
      for (int p = 0; p < NP; p++) ah0[p] = ah1[p] = make_float2(0.f, 0.f);
      const float2* wpa = g_Q2 + off + 768;
      const float* hp = s->XR1 + ks * HST;
      float2 wA0 = w2A0, wA1 = w2A1, wB0, wB1;
#pragma unroll 1
      for (int j = 0; j < 5; j++) {
        wB0 = __ldg(wpa); wB1 = __ldg(wpa + 32); wpa += 768;
        win2<NP>(wA0, wA1, hp, hp + 6 * HST, ah0, ah1);
        hp += 12 * HST;
        wA0 = __ldg(wpa); wA1 = __ldg(wpa + 32); wpa += 768;
        win2<NP>(wB0, wB1, hp, hp + 6 * HST, ah0, ah1);
        hp += 12 * HST;
      }
      win2<NP>(wA0, wA1, hp, hp + 6 * HST, ah0, ah1);
      wpart2<NP>(s->PH, c0, ks, ah0, ah1);
    }
    float4 w4u0 = __ldg(g_P4 + off), w4u1 = __ldg(g_P4 + off + 32);
    float4 w4t0 = __ldg(g_P4 + off + 768), w4t1 = __ldg(g_P4 + off + 800);
    __syncthreads();  // B3
    act2(s, t0, t, peer_h1);
    if (has1) act2(s, t1, t, peer_h1);
    CLUSTER_BAR();  // B4
    {  // ---- pass 3: node mix (row k3, pairs p3a/p3b) ----
      const float* rA = bufA + k3 * HST;
      const float* rB = bufB + k3 * HST;
      float hj[22];
      float4 a0 = *reinterpret_cast<const float4*>(rA);
      float4 a1 = *reinterpret_cast<const float4*>(rA + 4);
      float2 a2 = *reinterpret_cast<const float2*>(rA + 8);
      hj[0] = a0.x; hj[1] = a0.y; hj[2] = a0.z; hj[3] = a0.w;
      hj[4] = a1.x; hj[5] = a1.y; hj[6] = a1.z; hj[7] = a1.w;
      hj[8] = a2.x; hj[9] = a2.y;
      float4 b0 = *reinterpret_cast<const float4*>(rB);
      float4 b1 = *reinterpret_cast<const float4*>(rB + 4);
      float4 b2 = *reinterpret_cast<const float4*>(rB + 8);
      hj[10] = b0.x; hj[11] = b0.y; hj[12] = b0.z; hj[13] = b0.w;
      hj[14] = b1.x; hj[15] = b1.y; hj[16] = b1.z; hj[17] = b1.w;
      hj[18] = b2.x; hj[19] = b2.y; hj[20] = b2.z; hj[21] = b2.w;
      {
        const float2* ap = s->AP + p3a * 22;
        float2 acc = make_float2(0.f, 0.f);
#pragma unroll
        for (int j = 0; j < NN; j++)
          acc = ffma2(ap[j], make_float2(hj[j], hj[j]), acc);
        *reinterpret_cast<float2*>(s->XP + k3 * HST + 2 * p3a) = acc;
      }
      if (hasb) {
        const float2* ap = s->AP + p3b * 22;
        float2 acc = make_float2(0.f, 0.f);
#pragma unroll
        for (int j = 0; j < NN; j++)
          acc = ffma2(ap[j], make_float2(hj[j], hj[j]), acc);
        *reinterpret_cast<float2*>(s->XP + k3 * HST + 2 * p3b) = acc;
      }
    }
    __syncthreads();  // B5
    {  // ---- pass 4: layer2 z & r (fused XP·M + H2·W) ----
      float2 az0[NP], ar0[NP], az1[NP], ar1[NP];
#pragma unroll
      for (int p = 0; p < NP; p++) {
        az0[p] = ar0[p] = az1[p] = ar1[p] = make_float2(0.f, 0.f);
      }
      const float4* wpa = g_P4 + off + 1536;
      const float* xp = s->XP + ks * HST;
      const float* hp = s->H2 + ks * HST;
      float4 u0 = w4u0, u1 = w4u1, v0 = w4t0, v1 = w4t1;
      float4 n0, n1, m0, m1;
#pragma unroll 1
      for (int j = 0; j < 5; j++) {
        n0 = __ldg(wpa); n1 = __ldg(wpa + 32);
        m0 = __ldg(wpa + 768); m1 = __ldg(wpa + 800); wpa += 1536;
        win4<NP>(u0, u1, v0, v1, xp, hp, xp + 6 * HST, hp + 6 * HST, az0, ar0,
                 az1, ar1);
        xp += 12 * HST; hp += 12 * HST;
        u0 = __ldg(wpa); u1 = __ldg(wpa + 32);
        v0 = __ldg(wpa + 768); v1 = __ldg(wpa + 800); wpa += 1536;
        win4<NP>(n0, n1, m0, m1, xp, hp, xp + 6 * HST, hp + 6 * HST, az0, ar0,
                 az1, ar1);
        xp += 12 * HST; hp += 12 * HST;
      }
      win4<NP>(u0, u1, v0, v1, xp, hp, xp + 6 * HST, hp + 6 * HST, az0, ar0,
               az1, ar1);
      wpart2<NP>(s->PZ, c0, ks, az0, az1);
      wpart2<NP>(s->PR, c0, ks, ar0, ar1);
    }
    float4 w5A0 = __ldg(g_Q5 + off), w5A1 = __ldg(g_Q5 + off + 32);
    __syncthreads();  // B6
    act4(s, t0);
    if (has1) act4(s, t1);
    __syncthreads();  // B7
    {  // ---- pass 5: layer2 h-gate ----
      float2 ah0[NP], ah1[NP];
#pragma unroll
      for (int p = 0; p < NP; p++) ah0[p] = ah1[p] = make_float2(0.f, 0.f);
      const float4* wpa = g_Q5 + off + 768;
      const float* xp = s->XP + ks * HST;
      const float* rp = s->XR2 + ks * HST;
      float4 wA0 = w5A0, wA1 = w5A1, wB0, wB1;
#pragma unroll 1
      for (int j = 0; j < 5; j++) {
        wB0 = __ldg(wpa); wB1 = __ldg(wpa + 32); wpa += 768;
        win5<NP>(wA0, wA1, xp, rp, xp + 6 * HST, rp + 6 * HST, ah0, ah1);
        xp += 12 * HST; rp += 12 * HST;
        wA0 = __ldg(wpa); wA1 = __ldg(wpa + 32); wpa += 768;
        win5<NP>(wB0, wB1, xp, rp, xp + 6 * HST, rp + 6 * HST, ah0, ah1);
        xp += 12 * HST; rp += 12 * HST;
      }
      win5<NP>(wA0, wA1, xp, rp, xp + 6 * HST, rp + 6 * HST, ah0, ah1);
      wpart2<NP>(s->PH, c0, ks, ah0, ah1);
    }
    w1A0 = __ldg(g_Q1 + off);
    w1A1 = __ldg(g_Q1 + off + 32);
    __syncthreads();  // B8
    osum += act5<NP, RANK>(s, t0);
    if (has1) osum += act5<NP, RANK>(s, t1);
    // B9 removed: act5 reads PH/ZC/H2 only; pass1(t+1) writes PZ/PR and reads
    // H1loc — disjoint. The next PH write (pass2, t+1) is gated by B3(t+1);
    // ZC/H2/XR2 rewrites are gated by B5/B6/B7 of step t+1.
  }
  return osum;
}

// ---------------- main kernel: 2-CTA cluster per batch ----------------
__global__ void __launch_bounds__(THREADS, 1) __cluster_dims__(2, 1, 1)
tgcn_main(const float* __restrict__ x, const float* __restrict__ clsw,
          const float* __restrict__ clsb, float* __restrict__ out) {
  extern __shared__ __align__(16) unsigned char smraw[];
  SM* s = reinterpret_cast<SM*>(smraw);
  const int tid = threadIdx.x;
  const int rank = blockIdx.x & 1;
  const int b = blockIdx.x >> 1;
  const int w = tid >> 5;
  const int l = tid & 31;
  const int c0 = (w & 1) * 64 + l;
  const int ks = w >> 1;
  const int nploc = rank ? 6 : 5;
  const int gbase = rank ? 5 : 0;

  for (int i = tid; i < 128; i += THREADS) {
    s->uz[i] = g_c1[i];
    s->ur[i] = g_c1[128 + i];
    s->uh[i] = g_c1[256 + i];
    s->czb[i] = g_c1[384 + i];
    s->crb[i] = g_c1[512 + i];
    s->chb[i] = g_c1[640 + i];
    s->dzb[i] = g_c2[i];
    s->drb[i] = g_c2[128 + i];
    s->dhb[i] = g_c2[256 + i];
    s->clsw[i] = clsw[i];
  }
  for (int i = tid; i < SROWS * HST; i += THREADS) {
    s->H1loc[i] = 0.f;
    s->H1rem[i] = 0.f;
    s->H2[i] = 0.f;
    s->XR1[i] = 0.f;
    s->XP[i] = 0.f;
    s->XR2[i] = 0.f;
  }
  for (int i = tid; i < 6 * 22; i += THREADS) {
    int pl = i / 22, j = i - 22 * pl;
    float ax = 0.f, ay = 0.f;
    if (pl < nploc && j < NN) {
      int gp = gbase + pl;
      ax = g_A[(2 * gp) * NN + j];
      if (2 * gp + 1 < NN) ay = g_A[(2 * gp + 1) * NN + j];
    }
    s->AP[i] = make_float2(ax, ay);
  }
  if (tid == 0) s->peer_sum = 0.f;
  __syncthreads();

  const float* xb = x + (size_t)b * TT * NN;
  for (int i = tid; i < TT * nploc; i += THREADS) {
    int t = i / nploc, pl = i - t * nploc;
    const float2* ap = s->AP + pl * 22;
    float2 acc = make_float2(0.f, 0.f);
#pragma unroll
    for (int j = 0; j < NN; j++) {
      float xv = __ldg(xb + t * NN + j);
      acc = ffma2(ap[j], make_float2(xv, xv), acc);
    }
    s->YP[t * 6 + pl] = acc;
  }
  CLUSTER_BAR();  // peer smem initialized before any DSMEM push

  const unsigned peer_h1 = mapa_u32(smem_u32(s->H1rem), (unsigned)(rank ^ 1));
  const float* bufA = rank ? s->H1rem : s->H1loc;
  const float* bufB = rank ? s->H1loc : s->H1rem;

  float osum;
  if (rank)
    osum = run<6, 1>(s, c0, ks, tid, peer_h1, bufA, bufB);
  else
    osum = run<5, 0>(s, c0, ks, tid, peer_h1, bufA, bufB);

  __syncthreads();
  float v = osum * s->clsw[tid & 127];
#pragma unroll
  for (int off = 16; off > 0; off >>= 1)
    v += __shfl_down_sync(0xffffffffu, v, off);
  if ((tid & 31) == 0) s->red[tid >> 5] = v;
  __syncthreads();
  float S = 0.f;
  if (tid == 0) {
#pragma unroll
    for (int wI = 0; wI < 12; wI++) S += s->red[wI];
    if (rank == 1) stc32(mapa_u32(smem_u32(&s->peer_sum), 0u), S);
  }
  CLUSTER_BAR();
  if (rank == 0 && tid == 0)
    out[b] = (S + s->peer_sum) * (1.0f / (TT * NN)) + clsb[0];
}

// ---------------- launch ----------------
extern "C" void kernel_launch(void* const* d_in, const int* in_sizes, int n_in,
                              void* d_out, int out_size) {
  const float* x = (const float*)d_in[0];
  const int* ei = (const int*)d_in[1];
  const float* ew = (const float*)d_in[2];
  int E = in_sizes[1] / 2;

  prep_all<<<128, 256>>>(
      E, ei, ew, (const float*)d_in[3], (const float*)d_in[4],
      (const float*)d_in[5], (const float*)d_in[6], (const float*)d_in[7],
      (const float*)d_in[8], (const float*)d_in[9], (const float*)d_in[10],
      (const float*)d_in[11], (const float*)d_in[12], (const float*)d_in[13],
      (const float*)d_in[14], (const float*)d_in[15], (const float*)d_in[16],
      (const float*)d_in[17], (const float*)d_in[18], (const float*)d_in[19],
      (const float*)d_in[20], (const float*)d_in[21], (const float*)d_in[22],
      (const float*)d_in[23], (const float*)d_in[24], (const float*)d_in[25],
      (const float*)d_in[26]);

  cudaFuncSetAttribute(tgcn_main, cudaFuncAttributeMaxDynamicSharedMemorySize,
                       (int)sizeof(SM));
  tgcn_main<<<2 * BB, THREADS, sizeof(SM)>>>(
      x, (const float*)d_in[27], (const float*)d_in[28], (float*)d_out);
}